// round 14
// baseline (speedup 1.0000x reference)
#include <cuda_runtime.h>
#include <cuda_fp16.h>
#include <cstdint>

// Problem sizes (fixed by the reference)
#define M_ROWS 8192
#define IN_F   512
#define OUT_F  512
#define KDIM   (IN_F * 8)   // 4096

// ---------------------------------------------------------------------------
// Device scratch (allocation-free rule: __device__ globals)
// ---------------------------------------------------------------------------
__device__ __align__(16) __half g_Wh[(size_t)OUT_F * KDIM];  // 4 MB packed coeffs

// ---------------------------------------------------------------------------
// Kernel 1: pack W[o][i*8+k] = C[i][o][k], fp16.
// ---------------------------------------------------------------------------
__global__ void wpack_kernel(const float* __restrict__ coef) {
    int t = blockIdx.x * blockDim.x + threadIdx.x;
    if (t >= IN_F * OUT_F) return;
    int i = t & (IN_F - 1);
    int o = t >> 9;

    const float4* src = reinterpret_cast<const float4*>(coef + ((size_t)i * OUT_F + o) * 8);
    float4 c0 = __ldg(src);
    float4 c1 = __ldg(src + 1);

    __half2 h0 = __floats2half2_rn(c0.x, c0.y);
    __half2 h1 = __floats2half2_rn(c0.z, c0.w);
    __half2 h2 = __floats2half2_rn(c1.x, c1.y);
    __half2 h3 = __floats2half2_rn(c1.z, c1.w);
    *reinterpret_cast<uint4*>(g_Wh + (size_t)o * KDIM + i * 8) =
        make_uint4(*(uint32_t*)&h0, *(uint32_t*)&h1, *(uint32_t*)&h2, *(uint32_t*)&h3);
}

// ---------------------------------------------------------------------------
// Basis evaluation: uniform cubic B-spline, funnel-shift placement (8 halves).
// ---------------------------------------------------------------------------
__device__ __forceinline__ uint4 basis_eval(float xv, float g0, float invh) {
    float e  = __expf(2.0f * xv);
    float xn = 1.0f - 2.0f / (e + 1.0f);   // tanh(xv)

    float t  = (xn - g0) * invh;
    int   m  = (int)floorf(t);
    m = min(max(m, 3), 7);
    float u  = t - (float)m;

    float um = 1.0f - u;
    float u2 = u * u, u3 = u2 * u;
    const float s = 1.0f / 6.0f;
    float w0 = um * um * um * s;
    float w1 = (3.0f * u3 - 6.0f * u2 + 4.0f) * s;
    float w2 = (-3.0f * u3 + 3.0f * u2 + 3.0f * u + 1.0f) * s;
    float w3 = u3 * s;
    int j0 = m - 3;                        // in [0,4]

    __half2 hA = __floats2half2_rn(w0, w1);
    __half2 hB = __floats2half2_rn(w2, w3);
    uint32_t u0 = *(uint32_t*)&hA;
    uint32_t u1 = *(uint32_t*)&hB;

    uint32_t b  = (j0 & 1) << 4;
    uint32_t t0 = u0 << b;
    uint32_t t1 = __funnelshift_l(u0, u1, b);
    uint32_t t2 = __funnelshift_l(u1, 0u, b);
    int ws = j0 >> 1;

    uint4 o;
    o.x = (ws == 0) ? t0 : 0u;
    o.y = (ws == 0) ? t1 : ((ws == 1) ? t0 : 0u);
    o.z = (ws == 0) ? t2 : ((ws == 1) ? t1 : t0);
    o.w = (ws == 1) ? t2 : ((ws == 2) ? t1 : 0u);
    return o;
}

// ---------------------------------------------------------------------------
// Kernel 2: FUSED basis + GEMM.  A tile generated in-CTA into smem (no gmem A).
// CTA tile 224x128, grid (4,37) = 148 CTAs = one wave. 512 threads (16 warps,
// 2x8), warp tile 112x16. BK=64, 3-stage ring: B via cp.async, A via STS.
// gen placed BEFORE the MMA block so other warps absorb the MUFU latency.
// ---------------------------------------------------------------------------
#define BM 224
#define BN 128
#define BK 64                         // halves per K chunk = 8 features
#define ROWH 72                       // padded row stride (144B): LDSM conflict-free
#define STAGES 3
#define KT (KDIM / BK)                // 64
#define A_ST (BM * ROWH)              // 16128 halves
#define B_ST (BN * ROWH)              //  9216 halves
#define SMEM_BYTES (STAGES * (A_ST + B_ST) * 2)   // 152064
#define NTHREADS 512

__device__ __forceinline__ void cp16(void* smem, const void* gmem) {
    uint32_t sa = (uint32_t)__cvta_generic_to_shared(smem);
    asm volatile("cp.async.cg.shared.global [%0], [%1], 16;\n" :: "r"(sa), "l"(gmem));
}

__device__ __forceinline__ void ldsm_x4(uint32_t (&r)[4], uint32_t saddr) {
    asm volatile("ldmatrix.sync.aligned.m8n8.x4.shared.b16 {%0,%1,%2,%3}, [%4];"
                 : "=r"(r[0]), "=r"(r[1]), "=r"(r[2]), "=r"(r[3]) : "r"(saddr));
}

__device__ __forceinline__ void mma_f16(float (&d)[4], uint32_t a0, uint32_t a1,
                                        uint32_t a2, uint32_t a3,
                                        uint32_t b0, uint32_t b1) {
    asm volatile(
        "mma.sync.aligned.m16n8k16.row.col.f32.f16.f16.f32 "
        "{%0,%1,%2,%3}, {%4,%5,%6,%7}, {%8,%9}, {%0,%1,%2,%3};"
        : "+f"(d[0]), "+f"(d[1]), "+f"(d[2]), "+f"(d[3])
        : "r"(a0), "r"(a1), "r"(a2), "r"(a3), "r"(b0), "r"(b1));
}

__global__ void __launch_bounds__(NTHREADS, 1) gemm_kernel(float* __restrict__ C,
                                                           const float* __restrict__ x,
                                                           const float* __restrict__ grid) {
    extern __shared__ __half sm[];
    __half* AsBase = sm;
    __half* BsBase = sm + STAGES * A_ST;
    const uint32_t smem0 = (uint32_t)__cvta_generic_to_shared(sm);
    const uint32_t Bs0   = smem0 + STAGES * A_ST * 2;

    const int tid  = threadIdx.x;
    const int bm   = blockIdx.y * BM;
    const int bn   = blockIdx.x * BN;
    const int wid  = tid >> 5;
    const int lane = tid & 31;
    const int wm   = (wid >> 3) * 112;   // 0 / 112
    const int wn   = (wid & 7) * 16;     // 0..112
    const int gID  = lane >> 2;
    const int tg   = lane & 3;
    const int lrow = lane & 15;
    const int lcol = (lane >> 4) << 3;

    const float g0   = __ldg(grid);
    const float invh = 1.0f / (__ldg(grid + 1) - g0);

    // A-gen assignment: feat ii = tid&7, row base rb = tid>>3 (0..63),
    // rows rb, rb+64, rb+128, and rb+192 (only if rb < 32; 224 rows total).
    const int ii = tid & 7;
    const int rb = tid >> 3;
    const bool has4 = (rb < 32);
    const int r0c = min(bm + rb,       M_ROWS - 1);
    const int r1c = min(bm + rb + 64,  M_ROWS - 1);
    const int r2c = min(bm + rb + 128, M_ROWS - 1);
    const int r3c = min(bm + rb + 192, M_ROWS - 1);

    float xva[4];
    auto load_xv = [&](int c) {
        int f = c * 8 + ii;
        xva[0] = __ldg(x + (size_t)r0c * IN_F + f);
        xva[1] = __ldg(x + (size_t)r1c * IN_F + f);
        xva[2] = __ldg(x + (size_t)r2c * IN_F + f);
        if (has4) xva[3] = __ldg(x + (size_t)r3c * IN_F + f);
    };
    auto gen_a = [&](int s) {
        __half* As = AsBase + s * A_ST;
        uint4 o0 = basis_eval(xva[0], g0, invh);
        uint4 o1 = basis_eval(xva[1], g0, invh);
        uint4 o2 = basis_eval(xva[2], g0, invh);
        *reinterpret_cast<uint4*>(As + (rb)       * ROWH + ii * 8) = o0;
        *reinterpret_cast<uint4*>(As + (rb + 64)  * ROWH + ii * 8) = o1;
        *reinterpret_cast<uint4*>(As + (rb + 128) * ROWH + ii * 8) = o2;
        if (has4) {
            uint4 o3 = basis_eval(xva[3], g0, invh);
            *reinterpret_cast<uint4*>(As + (rb + 192) * ROWH + ii * 8) = o3;
        }
    };

    float acc[7][2][4];
#pragma unroll
    for (int a = 0; a < 7; ++a)
#pragma unroll
        for (int b = 0; b < 2; ++b)
#pragma unroll
            for (int c = 0; c < 4; ++c) acc[a][b][c] = 0.0f;

    auto issueB = [&](int s, int kt) {
        int k0 = kt * BK;
        __half* Bs = BsBase + s * B_ST;
#pragma unroll
        for (int i = 0; i < 2; ++i) {            // B: 128 rows x 8 chunks = 1024
            int id = tid + NTHREADS * i;
            int r = id >> 3, c = id & 7;
            cp16(Bs + r * ROWH + c * 8, g_Wh + (size_t)(bn + r) * KDIM + k0 + c * 8);
        }
        asm volatile("cp.async.commit_group;\n");
    };

    // prologue: A for chunks 0,1 (STS), B for chunks 0,1 (cp.async), x for 2
    load_xv(0); gen_a(0);
    load_xv(1); gen_a(1);
    issueB(0, 0);
    issueB(1, 1);
    load_xv(2);

    for (int kt = 0; kt < KT; ++kt) {
        if (kt < KT - 1) {
            asm volatile("cp.async.wait_group 1;\n");
        } else {
            asm volatile("cp.async.wait_group 0;\n");
        }
        __syncthreads();   // single barrier per chunk: orders STS + cp.async reuse

        const int s2 = (kt + 2) % STAGES;
        if (kt + 2 < KT) {
            issueB(s2, kt + 2);
            gen_a(s2);                 // before MMA: warps stagger, others absorb
            if (kt + 3 < KT) load_xv(kt + 3);
        }

        const int s = kt % STAGES;
        const uint32_t As_u = smem0 + (s * A_ST) * 2;
        const uint32_t Bs_u = Bs0 + (s * B_ST) * 2;

#pragma unroll
        for (int ks = 0; ks < BK; ks += 16) {
            uint32_t af[7][4];
#pragma unroll
            for (int mt = 0; mt < 7; ++mt)
                ldsm_x4(af[mt], As_u + ((wm + mt * 16 + lrow) * ROWH + ks + lcol) * 2);
            uint32_t bf[2][2];
            {
                uint32_t r[4];
                ldsm_x4(r, Bs_u + ((wn + lrow) * ROWH + ks + lcol) * 2);
                bf[0][0] = r[0]; bf[1][0] = r[1];
                bf[0][1] = r[2]; bf[1][1] = r[3];
            }
#pragma unroll
            for (int mt = 0; mt < 7; ++mt)
#pragma unroll
                for (int nt = 0; nt < 2; ++nt)
                    mma_f16(acc[mt][nt], af[mt][0], af[mt][1], af[mt][2], af[mt][3],
                            bf[nt][0], bf[nt][1]);
        }
        // no trailing barrier: next iteration's top barrier orders stage reuse
    }

    // Epilogue: guarded fp32 stores (padded M rows skipped).
#pragma unroll
    for (int mt = 0; mt < 7; ++mt) {
        int r0 = bm + wm + mt * 16 + gID;
#pragma unroll
        for (int nt = 0; nt < 2; ++nt) {
            int c = bn + wn + nt * 8 + tg * 2;
            if (r0 < M_ROWS)
                *reinterpret_cast<float2*>(C + (size_t)r0 * OUT_F + c) =
                    make_float2(acc[mt][nt][0], acc[mt][nt][1]);
            if (r0 + 8 < M_ROWS)
                *reinterpret_cast<float2*>(C + (size_t)(r0 + 8) * OUT_F + c) =
                    make_float2(acc[mt][nt][2], acc[mt][nt][3]);
        }
    }
}

// ---------------------------------------------------------------------------
extern "C" void kernel_launch(void* const* d_in, const int* in_sizes, int n_in,
                              void* d_out, int out_size) {
    const float* x    = (const float*)d_in[0];
    const float* coef = (const float*)d_in[1];
    const float* grid = (const float*)d_in[2];
    float* out = (float*)d_out;

    wpack_kernel<<<(IN_F * OUT_F + 255) / 256, 256>>>(coef);

    static int smem_set = 0;
    if (!smem_set) {
        cudaFuncSetAttribute(gemm_kernel, cudaFuncAttributeMaxDynamicSharedMemorySize,
                             SMEM_BYTES);
        smem_set = 1;
    }
    dim3 g(OUT_F / BN, 37);   // 4 x 37 = 148 CTAs = one full wave
    gemm_kernel<<<g, NTHREADS, SMEM_BYTES>>>(out, x, grid);
}